// round 4
// baseline (speedup 1.0000x reference)
#include <cuda_runtime.h>
#include <cuda_fp16.h>
#include <cstdint>
#include <cstddef>

// Problem constants
#define MB 8
#define TT 2048
#define CC 1024
#define MROWS (MB*TT)          // 16384
#define BTC (MROWS*CC)
#define BT4C (MROWS*4*CC)

// fp32 scratch
__device__ float g_h [BTC];
__device__ float g_k [BTC];
__device__ float g_v [BTC];
__device__ float g_r [BTC];
__device__ float g_x2[BTC];
__device__ float g_h2[BTC];
__device__ float g_s [BTC];
// fp16 hi/lo operand scratch
__device__ __half g_xk_h[BTC], g_xk_l[BTC];
__device__ __half g_xv_h[BTC], g_xv_l[BTC];
__device__ __half g_xr_h[BTC], g_xr_l[BTC];
__device__ __half g_ck_h[BTC], g_ck_l[BTC];
__device__ __half g_cr_h[BTC], g_cr_l[BTC];
__device__ __half g_kk_h[BT4C], g_kk_l[BT4C];
__device__ __half g_wkvr_h[3*CC*CC], g_wkvr_l[3*CC*CC];   // wtkT | wtvT | wtrT
__device__ __half g_wcks_h[5*CC*CC], g_wcks_l[5*CC*CC];   // wckT | wcrT
__device__ __half g_wcv_h [4*CC*CC], g_wcv_l [4*CC*CC];   // wcvT

// ---------------------------------------------------------------------------
// Helpers
// ---------------------------------------------------------------------------
__device__ __forceinline__ uint32_t smem_u32(const void* p){
    uint32_t a;
    asm("{ .reg .u64 t; cvta.to.shared.u64 t, %1; cvt.u32.u64 %0, t; }" : "=r"(a) : "l"(p));
    return a;
}
__device__ __forceinline__ void cp16(uint32_t dst, const void* src){
    asm volatile("cp.async.ca.shared.global [%0], [%1], 16;" :: "r"(dst), "l"(src));
}
#define CP_COMMIT() asm volatile("cp.async.commit_group;" ::: "memory")
#define CP_WAIT2()  asm volatile("cp.async.wait_group 2;" ::: "memory")
#define LDSM4(r0,r1,r2,r3,a) \
    asm volatile("ldmatrix.sync.aligned.m8n8.x4.shared.b16 {%0,%1,%2,%3}, [%4];" \
        : "=r"(r0),"=r"(r1),"=r"(r2),"=r"(r3) : "r"(a))

__device__ __forceinline__ void mma16816(float* d, const uint32_t* a, const uint32_t* b){
    asm volatile("mma.sync.aligned.m16n8k16.row.col.f32.f16.f16.f32 "
        "{%0,%1,%2,%3}, {%4,%5,%6,%7}, {%8,%9}, {%0,%1,%2,%3};"
        : "+f"(d[0]), "+f"(d[1]), "+f"(d[2]), "+f"(d[3])
        : "r"(a[0]), "r"(a[1]), "r"(a[2]), "r"(a[3]), "r"(b[0]), "r"(b[1]));
}

__device__ __forceinline__ void split_store4(float4 v, __half* hp_, __half* lp_){
    __half h0=__float2half_rn(v.x), h1=__float2half_rn(v.y);
    __half h2=__float2half_rn(v.z), h3=__float2half_rn(v.w);
    __half l0=__float2half_rn(v.x-__half2float(h0));
    __half l1=__float2half_rn(v.y-__half2float(h1));
    __half l2=__float2half_rn(v.z-__half2float(h2));
    __half l3=__float2half_rn(v.w-__half2float(h3));
    __half2* H = (__half2*)hp_; H[0]=__halves2half2(h0,h1); H[1]=__halves2half2(h2,h3);
    __half2* L = (__half2*)lp_; L[0]=__halves2half2(l0,l1); L[1]=__halves2half2(l2,l3);
}

// ---------------------------------------------------------------------------
// LayerNorm: one 256-thread block per row of C=1024 (fp32 out)
// ---------------------------------------------------------------------------
__global__ void __launch_bounds__(256) ln_kernel(
    const float* __restrict__ x, const float* __restrict__ g,
    const float* __restrict__ b, float* __restrict__ out)
{
    const int C = CC;
    size_t row = blockIdx.x;
    const float4* xr = (const float4*)(x + row * C);
    int tid = threadIdx.x;
    float4 v = xr[tid];

    float s = v.x + v.y + v.z + v.w;
    #pragma unroll
    for (int o = 16; o > 0; o >>= 1) s += __shfl_xor_sync(0xffffffffu, s, o);
    __shared__ float ws[8];
    if ((tid & 31) == 0) ws[tid >> 5] = s;
    __syncthreads();
    float mu = (ws[0]+ws[1]+ws[2]+ws[3]+ws[4]+ws[5]+ws[6]+ws[7]) * (1.0f / C);
    __syncthreads();

    float dx = v.x - mu, dy = v.y - mu, dz = v.z - mu, dw = v.w - mu;
    float s2 = dx*dx + dy*dy + dz*dz + dw*dw;
    #pragma unroll
    for (int o = 16; o > 0; o >>= 1) s2 += __shfl_xor_sync(0xffffffffu, s2, o);
    if ((tid & 31) == 0) ws[tid >> 5] = s2;
    __syncthreads();
    float var = (ws[0]+ws[1]+ws[2]+ws[3]+ws[4]+ws[5]+ws[6]+ws[7]) * (1.0f / C);
    float rstd = rsqrtf(var + 1e-5f);

    float4 gv = ((const float4*)g)[tid];
    float4 bv = ((const float4*)b)[tid];
    float4 o;
    o.x = dx * rstd * gv.x + bv.x;
    o.y = dy * rstd * gv.y + bv.y;
    o.z = dz * rstd * gv.z + bv.z;
    o.w = dw * rstd * gv.w + bv.w;
    ((float4*)(out + row * C))[tid] = o;
}

// ---------------------------------------------------------------------------
// Token-shift mixes -> fp16 hi/lo operand arrays
// ---------------------------------------------------------------------------
__device__ __forceinline__ float4 mixf4(float4 h, float4 hp, float4 m){
    float4 o;
    o.x = h.x*m.x + hp.x*(1.f-m.x);
    o.y = h.y*m.y + hp.y*(1.f-m.y);
    o.z = h.z*m.z + hp.z*(1.f-m.z);
    o.w = h.w*m.w + hp.w*(1.f-m.w);
    return o;
}
__global__ void __launch_bounds__(256) mix3_kernel(
    const float* __restrict__ h, const float* __restrict__ mk,
    const float* __restrict__ mv, const float* __restrict__ mr,
    __half* xkh, __half* xkl, __half* xvh, __half* xvl, __half* xrh, __half* xrl)
{
    int j = blockIdx.x * 256 + threadIdx.x;   // float4 index
    int row = j >> 8;
    int c4  = j & 255;
    float4 hv = ((const float4*)h)[j];
    float4 hp = make_float4(0.f,0.f,0.f,0.f);
    if ((row & (TT-1)) != 0) hp = ((const float4*)h)[j - 256];
    split_store4(mixf4(hv, hp, ((const float4*)mk)[c4]), xkh + j*4, xkl + j*4);
    split_store4(mixf4(hv, hp, ((const float4*)mv)[c4]), xvh + j*4, xvl + j*4);
    split_store4(mixf4(hv, hp, ((const float4*)mr)[c4]), xrh + j*4, xrl + j*4);
}
__global__ void __launch_bounds__(256) mix2_kernel(
    const float* __restrict__ h, const float* __restrict__ mk,
    const float* __restrict__ mr,
    __half* ckh, __half* ckl, __half* crh, __half* crl)
{
    int j = blockIdx.x * 256 + threadIdx.x;
    int row = j >> 8;
    int c4  = j & 255;
    float4 hv = ((const float4*)h)[j];
    float4 hp = make_float4(0.f,0.f,0.f,0.f);
    if ((row & (TT-1)) != 0) hp = ((const float4*)h)[j - 256];
    split_store4(mixf4(hv, hp, ((const float4*)mk)[c4]), ckh + j*4, ckl + j*4);
    split_store4(mixf4(hv, hp, ((const float4*)mr)[c4]), crh + j*4, crl + j*4);
}

// ---------------------------------------------------------------------------
// WKV sequential scan, fused x + r*y epilogue. 64 thr/block, 128 blocks.
// ---------------------------------------------------------------------------
__global__ void __launch_bounds__(64) wkv_kernel(
    const float* __restrict__ kp, const float* __restrict__ vp,
    const float* __restrict__ rp, const float* __restrict__ xp,
    const float* __restrict__ wdec, const float* __restrict__ ufst,
    float* __restrict__ out)
{
    int gid = blockIdx.x * 64 + threadIdx.x;   // 0..8191
    int b = gid >> 10;
    int c = gid & (CC - 1);
    float w = wdec[c], u = ufst[c];
    float aa = 0.0f, bb = 0.0f, pp = -1e38f;
    size_t idx = ((size_t)b * TT) * CC + c;
    #pragma unroll 2
    for (int t = 0; t < TT; t++, idx += CC) {
        float kk = kp[idx];
        float vv = vp[idx];
        float rr = rp[idx];
        float xx = xp[idx];
        float uk = u + kk;
        float p  = fmaxf(pp, uk);
        float e1 = __expf(pp - p);
        float e2 = __expf(uk - p);
        float y  = (e1 * aa + e2 * vv) / (e1 + e2);
        out[idx] = xx + rr * y;
        float pw = pp + w;
        float wk = w + kk;
        float p2 = fmaxf(pw, wk);
        float e1u = __expf(pw - p2);
        float e2u = __expf(wk - p2);
        aa = e1u * aa + e2u * vv;
        bb = e1u + e2u;
        pp = p2 + __logf(bb);
    }
}

// ---------------------------------------------------------------------------
// Weight transpose + fp16 split: src[R,Ccols] fp32 -> dstHi/dstLo[Ccols,R] fp16
// ---------------------------------------------------------------------------
__global__ void __launch_bounds__(256) tsplit_kernel(
    const float* __restrict__ src, __half* __restrict__ dstHi,
    __half* __restrict__ dstLo, int R, int Ccols)
{
    __shared__ float t[32][33];
    int r0 = blockIdx.y * 32, c0 = blockIdx.x * 32;
    int tx = threadIdx.x, ty = threadIdx.y;
    #pragma unroll
    for (int j = 0; j < 32; j += 8)
        t[ty + j][tx] = src[(size_t)(r0 + ty + j) * Ccols + c0 + tx];
    __syncthreads();
    #pragma unroll
    for (int j = 0; j < 32; j += 8) {
        float v = t[tx][ty + j];
        __half h = __float2half_rn(v);
        __half l = __float2half_rn(v - __half2float(h));
        size_t o = (size_t)(c0 + ty + j) * R + r0 + tx;
        dstHi[o] = h;
        dstLo[o] = l;
    }
}

// ---------------------------------------------------------------------------
// fp16 split-GEMM core: C[M,N] = epi(A@Bt^T) with A,Bt fp16 hi/lo pairs.
// CTA tile 256x128, k-step 16, 4-stage cp.async pipeline, ldmatrix frags.
// Smem stage layout: per operand-half, 8-row blocks of 16 16B chunks:
//   phys(row, c) = (row>>3)*256 + ((c<<3 | (row&7))<<4), c = k-half (0/1).
// ---------------------------------------------------------------------------
#define CTM 256
#define CTN 128
#define ST_A 8192
#define ST_B 4096
#define STAGE_BYTES 24576
#define GSMEM (STAGE_BYTES*4)   // 98304

#define EPI_NONE 0
#define EPI_SIGMOID 1
#define EPI_RELUSQ 2
#define EPI_RESID 3

template<int EPI>
__device__ __forceinline__ void gemm_core(
    const __half* __restrict__ Ahi, const __half* __restrict__ Alo,
    const __half* __restrict__ Bhi, const __half* __restrict__ Blo,
    int K, int m0, int n0B,
    float* __restrict__ outF, const float* __restrict__ resid,
    const float* __restrict__ gate,
    __half* __restrict__ outHi, __half* __restrict__ outLo,
    int Nout, int n0o)
{
    extern __shared__ char smem[];
    const uint32_t sbase = smem_u32(smem);
    const int tid = threadIdx.x;
    const int lane = tid & 31, wid = tid >> 5;
    const int wm = wid & 3, wn = wid >> 2;
    const int NS = K >> 4;

    auto load_stage = [&](int s, int buf){
        const int k0 = s << 4;
        uint32_t st = sbase + (uint32_t)buf * STAGE_BYTES;
        #pragma unroll
        for (int l = 0; l < 2; l++) {
            int chk = l*256 + tid;                  // 0..511
            int row = chk >> 1, c = chk & 1;
            uint32_t d = (uint32_t)((row>>3)<<8) | (uint32_t)((((c<<3)|(row&7)))<<4);
            size_t go = (size_t)(m0+row)*K + k0 + c*8;
            cp16(st + d,        Ahi + go);
            cp16(st + ST_A + d, Alo + go);
        }
        {
            int row = tid >> 1, c = tid & 1;        // 0..255 chunks
            uint32_t d = (uint32_t)((row>>3)<<8) | (uint32_t)((((c<<3)|(row&7)))<<4);
            size_t go = (size_t)(n0B+row)*K + k0 + c*8;
            cp16(st + 2*ST_A + d,        Bhi + go);
            cp16(st + 2*ST_A + ST_B + d, Blo + go);
        }
    };

    float acc[4][8][4];
    #pragma unroll
    for (int mi = 0; mi < 4; mi++)
        #pragma unroll
        for (int ni = 0; ni < 8; ni++)
            #pragma unroll
            for (int c = 0; c < 4; c++) acc[mi][ni][c] = 0.0f;

    load_stage(0, 0); CP_COMMIT();
    load_stage(1, 1); CP_COMMIT();
    load_stage(2, 2); CP_COMMIT();

    const int rl = lane & 15, chh = lane >> 4;
    const uint32_t bpart = (uint32_t)(((rl>>3)<<8) | (((chh<<3)|(rl&7))<<4));

    for (int s = 0; s < NS; s++) {
        int buf = s & 3;
        CP_WAIT2();
        __syncthreads();
        if (s + 3 < NS) load_stage(s + 3, (s + 3) & 3);
        CP_COMMIT();

        uint32_t stA = sbase + (uint32_t)buf * STAGE_BYTES;
        uint32_t stB = stA + 2*ST_A;

        uint32_t ahi[4][4], bh[8][2];
        #pragma unroll
        for (int mi = 0; mi < 4; mi++) {
            uint32_t ad = stA + (uint32_t)((wm*8 + mi*2) << 8) + bpart;
            LDSM4(ahi[mi][0], ahi[mi][1], ahi[mi][2], ahi[mi][3], ad);
        }
        #pragma unroll
        for (int g = 0; g < 4; g++) {
            uint32_t bd = stB + (uint32_t)((wn*8 + g*2) << 8) + bpart;
            uint32_t r0, r1, r2, r3;
            LDSM4(r0, r1, r2, r3, bd);
            bh[2*g][0] = r0; bh[2*g][1] = r2;
            bh[2*g+1][0] = r1; bh[2*g+1][1] = r3;
        }
        // hi*hi
        #pragma unroll
        for (int mi = 0; mi < 4; mi++)
            #pragma unroll
            for (int ni = 0; ni < 8; ni++)
                mma16816(acc[mi][ni], ahi[mi], bh[ni]);
        // hi*lo
        {
            uint32_t bl[8][2];
            #pragma unroll
            for (int g = 0; g < 4; g++) {
                uint32_t bd = stB + ST_B + (uint32_t)((wn*8 + g*2) << 8) + bpart;
                uint32_t r0, r1, r2, r3;
                LDSM4(r0, r1, r2, r3, bd);
                bl[2*g][0] = r0; bl[2*g][1] = r2;
                bl[2*g+1][0] = r1; bl[2*g+1][1] = r3;
            }
            #pragma unroll
            for (int mi = 0; mi < 4; mi++)
                #pragma unroll
                for (int ni = 0; ni < 8; ni++)
                    mma16816(acc[mi][ni], ahi[mi], bl[ni]);
        }
        // lo*hi
        {
            uint32_t alo[4][4];
            #pragma unroll
            for (int mi = 0; mi < 4; mi++) {
                uint32_t ad = stA + ST_A + (uint32_t)((wm*8 + mi*2) << 8) + bpart;
                LDSM4(alo[mi][0], alo[mi][1], alo[mi][2], alo[mi][3], ad);
            }
            #pragma unroll
            for (int mi = 0; mi < 4; mi++)
                #pragma unroll
                for (int ni = 0; ni < 8; ni++)
                    mma16816(acc[mi][ni], alo[mi], bh[ni]);
        }
    }

    // ---- epilogue
    #pragma unroll
    for (int mi = 0; mi < 4; mi++) {
        int r0 = m0 + wm*64 + mi*16 + (lane >> 2);
        #pragma unroll
        for (int ni = 0; ni < 8; ni++) {
            int c0 = n0o + wn*64 + ni*8 + (lane & 3)*2;
            float v0 = acc[mi][ni][0], v1 = acc[mi][ni][1];
            float v2 = acc[mi][ni][2], v3 = acc[mi][ni][3];
            size_t i0 = (size_t)r0 * Nout + c0;
            size_t i1 = (size_t)(r0 + 8) * Nout + c0;
            if (EPI == EPI_SIGMOID) {
                v0 = 1.f/(1.f+__expf(-v0)); v1 = 1.f/(1.f+__expf(-v1));
                v2 = 1.f/(1.f+__expf(-v2)); v3 = 1.f/(1.f+__expf(-v3));
            } else if (EPI == EPI_RELUSQ) {
                v0 = fmaxf(v0,0.f); v1 = fmaxf(v1,0.f);
                v2 = fmaxf(v2,0.f); v3 = fmaxf(v3,0.f);
                v0 *= v0; v1 *= v1; v2 *= v2; v3 *= v3;
                __half h0=__float2half_rn(v0), h1=__float2half_rn(v1);
                __half h2=__float2half_rn(v2), h3=__float2half_rn(v3);
                __half l0=__float2half_rn(v0-__half2float(h0));
                __half l1=__float2half_rn(v1-__half2float(h1));
                __half l2=__float2half_rn(v2-__half2float(h2));
                __half l3=__float2half_rn(v3-__half2float(h3));
                *(__half2*)(outHi + i0) = __halves2half2(h0,h1);
                *(__half2*)(outLo + i0) = __halves2half2(l0,l1);
                *(__half2*)(outHi + i1) = __halves2half2(h2,h3);
                *(__half2*)(outLo + i1) = __halves2half2(l2,l3);
                continue;
            }
            if (EPI == EPI_RESID) {
                float2 rz0 = *(const float2*)(resid + i0);
                float2 rz1 = *(const float2*)(resid + i1);
                float2 gz0 = *(const float2*)(gate  + i0);
                float2 gz1 = *(const float2*)(gate  + i1);
                v0 = rz0.x + gz0.x*v0; v1 = rz0.y + gz0.y*v1;
                v2 = rz1.x + gz1.x*v2; v3 = rz1.y + gz1.y*v3;
            }
            *(float2*)(outF + i0) = make_float2(v0, v1);
            *(float2*)(outF + i1) = make_float2(v2, v3);
        }
    }
}

// Fused k|v|r GEMM: N-blocks 0-7 -> k, 8-15 -> v, 16-23 -> sigmoid r
__global__ void __launch_bounds__(256, 1) gemm_kvr(
    const __half* xkh, const __half* xkl, const __half* xvh, const __half* xvl,
    const __half* xrh, const __half* xrl,
    const __half* Bh, const __half* Bl,
    float* outk, float* outv, float* outr)
{
    int seg = blockIdx.x >> 3;
    int m0  = blockIdx.y * CTM;
    int n0B = blockIdx.x * CTN;
    int n0o = (blockIdx.x & 7) * CTN;
    const __half* Ah = (seg == 0) ? xkh : (seg == 1) ? xvh : xrh;
    const __half* Al = (seg == 0) ? xkl : (seg == 1) ? xvl : xrl;
    float* o = (seg == 0) ? outk : (seg == 1) ? outv : outr;
    if (seg == 2)
        gemm_core<EPI_SIGMOID>(Ah, Al, Bh, Bl, CC, m0, n0B, o, nullptr, nullptr, nullptr, nullptr, CC, n0o);
    else
        gemm_core<EPI_NONE>(Ah, Al, Bh, Bl, CC, m0, n0B, o, nullptr, nullptr, nullptr, nullptr, CC, n0o);
}

// Fused kk|s GEMM: N-blocks 0-31 -> relu^2 kk (fp16 hi/lo), 32-39 -> sigmoid s
__global__ void __launch_bounds__(256, 1) gemm_cks(
    const __half* ckh, const __half* ckl, const __half* crh, const __half* crl,
    const __half* Bh, const __half* Bl,
    __half* kkh, __half* kkl, float* outs)
{
    int bx = blockIdx.x;
    int m0 = blockIdx.y * CTM;
    int n0B = bx * CTN;
    if (bx < 32)
        gemm_core<EPI_RELUSQ>(ckh, ckl, Bh, Bl, CC, m0, n0B, nullptr, nullptr, nullptr,
                              kkh, kkl, 4*CC, bx*CTN);
    else
        gemm_core<EPI_SIGMOID>(crh, crl, Bh, Bl, CC, m0, n0B, outs, nullptr, nullptr,
                               nullptr, nullptr, CC, (bx-32)*CTN);
}

// Final GEMM: out = x2 + s * (kk @ w_cv), K = 4096
__global__ void __launch_bounds__(256, 1) gemm_out(
    const __half* kkh, const __half* kkl,
    const __half* Bh, const __half* Bl,
    float* out, const float* x2, const float* sg)
{
    int m0 = blockIdx.y * CTM;
    int n0 = blockIdx.x * CTN;
    gemm_core<EPI_RESID>(kkh, kkl, Bh, Bl, 4*CC, m0, n0, out, x2, sg,
                         nullptr, nullptr, CC, n0);
}

// ---------------------------------------------------------------------------
// Host launcher
// ---------------------------------------------------------------------------
template<typename T>
static T* symaddr(const void* sym)
{
    void* p = nullptr;
    cudaGetSymbolAddress(&p, sym);
    return (T*)p;
}

extern "C" void kernel_launch(void* const* d_in, const int* in_sizes, int n_in,
                              void* d_out, int out_size)
{
    const float* x      = (const float*)d_in[0];
    const float* tdecay = (const float*)d_in[1];
    const float* tfirst = (const float*)d_in[2];
    const float* w_tk   = (const float*)d_in[3];
    const float* w_tv   = (const float*)d_in[4];
    const float* w_tr   = (const float*)d_in[5];
    const float* w_ck   = (const float*)d_in[6];
    const float* w_cv   = (const float*)d_in[7];
    const float* w_cr   = (const float*)d_in[8];
    const float* ln1_g  = (const float*)d_in[9];
    const float* ln1_b  = (const float*)d_in[10];
    const float* ln2_g  = (const float*)d_in[11];
    const float* ln2_b  = (const float*)d_in[12];
    const float* mix_k  = (const float*)d_in[13];
    const float* mix_v  = (const float*)d_in[14];
    const float* mix_r  = (const float*)d_in[15];
    const float* cmix_k = (const float*)d_in[16];
    const float* cmix_r = (const float*)d_in[17];
    float* out = (float*)d_out;

    float* h   = symaddr<float>(g_h);
    float* k   = symaddr<float>(g_k);
    float* v   = symaddr<float>(g_v);
    float* r   = symaddr<float>(g_r);
    float* x2  = symaddr<float>(g_x2);
    float* h2  = symaddr<float>(g_h2);
    float* s   = symaddr<float>(g_s);
    __half* xkh = symaddr<__half>(g_xk_h); __half* xkl = symaddr<__half>(g_xk_l);
    __half* xvh = symaddr<__half>(g_xv_h); __half* xvl = symaddr<__half>(g_xv_l);
    __half* xrh = symaddr<__half>(g_xr_h); __half* xrl = symaddr<__half>(g_xr_l);
    __half* ckh = symaddr<__half>(g_ck_h); __half* ckl = symaddr<__half>(g_ck_l);
    __half* crh = symaddr<__half>(g_cr_h); __half* crl = symaddr<__half>(g_cr_l);
    __half* kkh = symaddr<__half>(g_kk_h); __half* kkl = symaddr<__half>(g_kk_l);
    __half* wkvrh = symaddr<__half>(g_wkvr_h); __half* wkvrl = symaddr<__half>(g_wkvr_l);
    __half* wcksh = symaddr<__half>(g_wcks_h); __half* wcksl = symaddr<__half>(g_wcks_l);
    __half* wcvh  = symaddr<__half>(g_wcv_h);  __half* wcvl  = symaddr<__half>(g_wcv_l);

    cudaFuncSetAttribute((const void*)gemm_kvr, cudaFuncAttributeMaxDynamicSharedMemorySize, GSMEM);
    cudaFuncSetAttribute((const void*)gemm_cks, cudaFuncAttributeMaxDynamicSharedMemorySize, GSMEM);
    cudaFuncSetAttribute((const void*)gemm_out, cudaFuncAttributeMaxDynamicSharedMemorySize, GSMEM);

    const int M = MROWS;
    dim3 tb(32, 8);
    const int mixg = (BTC/4) / 256;

    // 0-2) transpose+split time-mix weights into concat buffer [3072,1024]
    tsplit_kernel<<<dim3(CC/32, CC/32), tb>>>(w_tk, wkvrh,           wkvrl,           CC, CC);
    tsplit_kernel<<<dim3(CC/32, CC/32), tb>>>(w_tv, wkvrh + CC*CC,   wkvrl + CC*CC,   CC, CC);
    tsplit_kernel<<<dim3(CC/32, CC/32), tb>>>(w_tr, wkvrh + 2*CC*CC, wkvrl + 2*CC*CC, CC, CC);

    // 3) h = LN1(x);  4) token-shift mixes (fp16 split)
    ln_kernel<<<M, 256>>>(x, ln1_g, ln1_b, h);
    mix3_kernel<<<mixg, 256>>>(h, mix_k, mix_v, mix_r, xkh, xkl, xvh, xvl, xrh, xrl);

    // 5) fused k|v|r GEMM  (6th launch -> ncu capture target)
    gemm_kvr<<<dim3(24, M/CTM), 256, GSMEM>>>(xkh, xkl, xvh, xvl, xrh, xrl,
                                              wkvrh, wkvrl, k, v, r);

    // 6) x2 = x + r * WKV(k, v)
    wkv_kernel<<<128, 64>>>(k, v, r, x, tdecay, tfirst, x2);

    // 7) h2 = LN2(x2);  8) channel mixes
    ln_kernel<<<M, 256>>>(x2, ln2_g, ln2_b, h2);
    mix2_kernel<<<mixg, 256>>>(h2, cmix_k, cmix_r, ckh, ckl, crh, crl);

    // 9-11) transpose+split channel weights: [4096+1024,1024] concat and [1024,4096]
    tsplit_kernel<<<dim3(4*CC/32, CC/32), tb>>>(w_ck, wcksh,            wcksl,            CC, 4*CC);
    tsplit_kernel<<<dim3(CC/32, CC/32),   tb>>>(w_cr, wcksh + 4*CC*CC,  wcksl + 4*CC*CC,  CC, CC);
    tsplit_kernel<<<dim3(CC/32, 4*CC/32), tb>>>(w_cv, wcvh,             wcvl,             4*CC, CC);

    // 12) fused kk|s GEMM: kk = relu(ck@w_ck)^2 (fp16 split), s = sigmoid(cr@w_cr)
    gemm_cks<<<dim3(40, M/CTM), 256, GSMEM>>>(ckh, ckl, crh, crl, wcksh, wcksl,
                                              kkh, kkl, s);

    // 13) out = x2 + s * (kk @ w_cv), K = 4096
    gemm_out<<<dim3(8, M/CTM), 256, GSMEM>>>(kkh, kkl, wcvh, wcvl, out, x2, s);
}